// round 12
// baseline (speedup 1.0000x reference)
#include <cuda_runtime.h>

#define NS 8
#define NC 128
#define KT 32
#define KF 16
#define FREQ 256
#define NFW 15
#define THR 15.0f
#define LPRE 431
#define NPOT 6400
#define MARGIN 0.05f
#define NCAND 16

#define TP 33
#define RP 17
#define RROW_OFF  14224          /* tile = 431*33 = 14223 */
#define S_OFF     21552          /* Rrow = 431*17 = 7327 */
#define X2_OFF    27952          /* variance (lazy) */
#define RROW2_OFF 34352          /* lazy */
#define XP_OFF    41680          /* xpatch[16][512] */
#define SMEM_F    49872          /* 199,488 bytes */

__device__ unsigned g_poolw[NS * NFW * 4];
__device__ unsigned g_done;

__global__ __launch_bounds__(512, 1)
void spyke_kernel(const float* __restrict__ X, const float* __restrict__ W,
                  int* __restrict__ out)
{
    extern __shared__ float sm[];
    float* tile   = sm;
    float* Rrow   = sm + RROW_OFF;
    float* Sarr   = sm + S_OFF;
    float* Varr   = sm + X2_OFF;
    float* Rrow2  = sm + RROW2_OFF;
    float* xpatch = sm + XP_OFF;

    __shared__ unsigned long long s_cand[NCAND];
    __shared__ int s_p[NCAND];
    __shared__ float s_cw[NC], s_cb[NC];
    __shared__ unsigned s_pool[4];
    __shared__ int s_sig_i, s_rcnt, s_last, s_any, s_key0, s_key1, s_cfired;
    __shared__ int s_rem[NC];

    const int s = blockIdx.x / NFW, fwin = blockIdx.x % NFW;
    const int tid = threadIdx.x, sec = s * 400;
    const int lane = tid & 31, wid = tid >> 5;

    if (tid < NCAND) s_cand[tid] = 0ULL;
    if (tid < 4) s_pool[tid] = 0u;
    if (tid == 0) { s_rcnt = 0; s_sig_i = 0; }

    const float* Wsec = W + (size_t)s * NC * 512;

    // ---- prefetch W section into L2 (overlaps with prep) ----
    for (int i = tid; i < 2048; i += 512)
        asm volatile("prefetch.global.L2 [%0];" :: "l"(Wsec + i * 32));

    // ---- stage X window: float4 loads ----
    {
        const float4* X4 = (const float4*)X;
        for (int i = tid; i < LPRE * 8; i += 512) {
            int r = i >> 3, c = i & 7;
            float4 v = X4[(sec + r) * 64 + fwin * 4 + c];
            float* dst = tile + r * TP + c * 4;
            dst[0] = v.x; dst[1] = v.y; dst[2] = v.z; dst[3] = v.w;
        }
    }
    __syncthreads();

    // ---- row sliding sums over kf-window of 16 ----
    if (tid < LPRE) {
        float a = 0.f;
        #pragma unroll
        for (int c = 0; c < 16; ++c) a += tile[tid*TP + c];
        Rrow[tid*RP] = a;
        #pragma unroll 5
        for (int f = 1; f < 16; ++f) {
            a += tile[tid*TP + f + 15] - tile[tid*TP + f - 1];
            Rrow[tid*RP + f] = a;
        }
    }
    __syncthreads();

    // ---- column sliding over kt-window of 32: S + per-region argmax ----
    if (tid < 400) {
        int f = tid & 15, t0 = (tid >> 4) * 16;
        float a = 0.f;
        #pragma unroll 8
        for (int k = 0; k < 32; ++k) a += Rrow[(t0+k)*RP+f];
        unsigned long long lkey[2] = {0ULL, 0ULL};
        int reg0 = t0 / 25;
        for (int t = t0; t < t0 + 16; ++t) {
            int p = t*16 + f;
            Sarr[p] = a;
            unsigned long long key =
                ((unsigned long long)__float_as_uint(a) << 13) | (unsigned)p;
            int ri = (t / 25) - reg0;
            if (key > lkey[ri]) lkey[ri] = key;
            if (t <= 398) a += Rrow[(t+32)*RP+f] - Rrow[t*RP+f];
        }
        atomicMax(&s_cand[reg0], lkey[0]);
        if (lkey[1] && reg0 + 1 < NCAND) atomicMax(&s_cand[reg0 + 1], lkey[1]);
    }
    __syncthreads();

    // ---- sort candidates descending by S ----
    if (tid < NCAND) {
        unsigned long long mykey = s_cand[tid];
        int rank = 0;
        for (int j = 0; j < NCAND; ++j) rank += (s_cand[j] > mykey);
        s_p[rank] = (int)(mykey & 8191ULL);
    }
    __syncthreads();

    // ---- stage all 16 candidate patches ----
    {
        const int gr = tid >> 4, gc = tid & 15;
        #pragma unroll
        for (int k = 0; k < NCAND; ++k) {
            int p = s_p[k], t = p >> 4, f = p & 15;
            xpatch[k * 512 + tid] = tile[(t + gr) * TP + f + gc];
        }
    }
    __syncthreads();

    // ---- per-warp probes: NO CTA barriers; warps retire independently ----
    const float4* Ws4 = (const float4*)Wsec;
    unsigned unres = 0xffu;

    {   // candidate 0: one probe per channel
        const float4* xp4 = (const float4*)xpatch;
        float4 x0 = xp4[lane], x1 = xp4[lane+32], x2 = xp4[lane+64], x3 = xp4[lane+96];
        #pragma unroll
        for (int j = 0; j < 8; ++j) {
            int c = wid * 8 + j;
            const float4* Wc = Ws4 + (size_t)c * 128;
            float4 w0 = Wc[lane], w1 = Wc[lane+32], w2 = Wc[lane+64], w3 = Wc[lane+96];
            float a = 0.f;
            a = fmaf(w0.x, x0.x, a); a = fmaf(w0.y, x0.y, a); a = fmaf(w0.z, x0.z, a); a = fmaf(w0.w, x0.w, a);
            a = fmaf(w1.x, x1.x, a); a = fmaf(w1.y, x1.y, a); a = fmaf(w1.z, x1.z, a); a = fmaf(w1.w, x1.w, a);
            a = fmaf(w2.x, x2.x, a); a = fmaf(w2.y, x2.y, a); a = fmaf(w2.z, x2.z, a); a = fmaf(w2.w, x2.w, a);
            a = fmaf(w3.x, x3.x, a); a = fmaf(w3.y, x3.y, a); a = fmaf(w3.z, x3.z, a); a = fmaf(w3.w, x3.w, a);
            #pragma unroll
            for (int d = 16; d; d >>= 1) a += __shfl_xor_sync(~0u, a, d);
            if (a >= THR) {
                unres &= ~(1u << j);
                if (lane == 0) atomicOr(&s_pool[c >> 5], 1u << (c & 31));
            }
        }
    }
    // candidates 1..15 in chunks of 4 (fire = max over chunk >= THR)
    for (int ka = 1; ka < NCAND && unres; ka += 4) {
        #pragma unroll
        for (int j = 0; j < 8; ++j) {
            if (!((unres >> j) & 1u)) continue;
            int c = wid * 8 + j;
            const float4* Wc = Ws4 + (size_t)c * 128;
            float4 w0 = Wc[lane], w1 = Wc[lane+32], w2 = Wc[lane+64], w3 = Wc[lane+96];
            float acc[4];
            #pragma unroll
            for (int u = 0; u < 4; ++u) {
                int k = ka + u;
                bool act = (k < NCAND);
                const float4* xp4 = (const float4*)(xpatch + (act ? k : ka) * 512);
                float a = 0.f;
                float4 x0 = xp4[lane];
                a = fmaf(w0.x, x0.x, a); a = fmaf(w0.y, x0.y, a); a = fmaf(w0.z, x0.z, a); a = fmaf(w0.w, x0.w, a);
                float4 x1 = xp4[lane+32];
                a = fmaf(w1.x, x1.x, a); a = fmaf(w1.y, x1.y, a); a = fmaf(w1.z, x1.z, a); a = fmaf(w1.w, x1.w, a);
                float4 x2 = xp4[lane+64];
                a = fmaf(w2.x, x2.x, a); a = fmaf(w2.y, x2.y, a); a = fmaf(w2.z, x2.z, a); a = fmaf(w2.w, x2.w, a);
                float4 x3 = xp4[lane+96];
                a = fmaf(w3.x, x3.x, a); a = fmaf(w3.y, x3.y, a); a = fmaf(w3.z, x3.z, a); a = fmaf(w3.w, x3.w, a);
                acc[u] = act ? a : -1e30f;
            }
            #pragma unroll
            for (int d = 16; d; d >>= 1) {
                acc[0] += __shfl_xor_sync(~0u, acc[0], d);
                acc[1] += __shfl_xor_sync(~0u, acc[1], d);
                acc[2] += __shfl_xor_sync(~0u, acc[2], d);
                acc[3] += __shfl_xor_sync(~0u, acc[3], d);
            }
            float m = fmaxf(fmaxf(acc[0], acc[1]), fmaxf(acc[2], acc[3]));
            if (m >= THR) {
                unres &= ~(1u << j);
                if (lane == 0) atomicOr(&s_pool[c >> 5], 1u << (c & 31));
            }
        }
    }
    __syncthreads();

    // ================= rigorous cold path (unfired channels) =================
    if ((s_pool[0] & s_pool[1] & s_pool[2] & s_pool[3]) != 0xffffffffu) {
        if (tid < LPRE) {
            float a2 = 0.f;
            #pragma unroll
            for (int c = 0; c < 16; ++c) { float x = tile[tid*TP + c]; a2 += x*x; }
            Rrow2[tid*RP] = a2;
            for (int f = 1; f < 16; ++f) {
                float xo = tile[tid*TP + f - 1], xn = tile[tid*TP + f + 15];
                a2 += xn*xn - xo*xo;
                Rrow2[tid*RP + f] = a2;
            }
        }
        __syncthreads();
        if (tid < 400) {
            int f = tid & 15, t0 = (tid >> 4) * 16;
            float a2 = 0.f;
            for (int k = 0; k < 32; ++k) a2 += Rrow2[(t0+k)*RP+f];
            float lsig = 0.f;
            for (int t = t0; t < t0 + 16; ++t) {
                int p = t*16 + f;
                float S = Sarr[p];
                float var = fmaxf(a2 - S*S*(1.0f/512.0f), 0.f);
                Varr[p] = var;
                lsig = fmaxf(lsig, var);
                if (t <= 398) a2 += Rrow2[(t+32)*RP+f] - Rrow2[t*RP+f];
            }
            atomicMax(&s_sig_i, __float_as_int(lsig));
        }
        __syncthreads();

        for (int c = wid; c < NC; c += 16) {
            if ((s_pool[c >> 5] >> (c & 31)) & 1u) continue;
            const float4* Wc = Ws4 + (size_t)c * 128;
            float4 w0 = Wc[lane], w1 = Wc[lane+32], w2 = Wc[lane+64], w3 = Wc[lane+96];
            float ws = (w0.x+w0.y+w0.z+w0.w) + (w1.x+w1.y+w1.z+w1.w)
                     + (w2.x+w2.y+w2.z+w2.w) + (w3.x+w3.y+w3.z+w3.w);
            float wq = (w0.x*w0.x+w0.y*w0.y+w0.z*w0.z+w0.w*w0.w)
                     + (w1.x*w1.x+w1.y*w1.y+w1.z*w1.z+w1.w*w1.w)
                     + (w2.x*w2.x+w2.y*w2.y+w2.z*w2.z+w2.w*w2.w)
                     + (w3.x*w3.x+w3.y*w3.y+w3.z*w3.z+w3.w*w3.w);
            #pragma unroll
            for (int d = 16; d; d >>= 1) {
                ws += __shfl_xor_sync(~0u, ws, d);
                wq += __shfl_xor_sync(~0u, wq, d);
            }
            if (lane == 0) {
                s_cw[c] = ws;
                s_cb[c] = sqrtf(fmaxf(wq - ws*ws*(1.0f/512.0f), 0.f));
            }
        }
        __syncthreads();

        const float Smax   = Sarr[s_p[0]];
        const float sigMax = sqrtf(__int_as_float(s_sig_i));
        if (tid < NC && !((s_pool[tid >> 5] >> (tid & 31)) & 1u)) {
            if (s_cw[tid] * Smax * (1.0f/512.0f) + s_cb[tid] * sigMax >= THR - MARGIN)
                s_rem[atomicAdd(&s_rcnt, 1)] = tid;
        }
        __syncthreads();

        float* wbuf = xpatch;
        const int rbase = (lane >> 4);
        const int cofs  = (lane & 15);

        for (int ri = 0; ri < s_rcnt; ++ri) {
            const int cc = s_rem[ri];
            if (tid < 128)
                ((float4*)wbuf)[tid] = Ws4[(size_t)cc * 128 + tid];
            if (tid == 0) s_cfired = 0;
            __syncthreads();

            const float cw = s_cw[cc], cb2 = s_cb[cc] * s_cb[cc];
            volatile int* cf = &s_cfired;
            int fired = 0;
            for (int p0 = wid * 400; p0 < wid * 400 + 400 && !fired && !*cf; p0 += 32) {
                int p = p0 + lane;
                float S   = Sarr[p];
                float var = Varr[p];
                float base = cw * S * (1.0f/512.0f);
                float d1 = base - (THR + MARGIN);
                float d2 = (THR - MARGIN) - base;
                bool fl  = (d1 >= 0.f) && (d1*d1 >= cb2*var);
                bool amb = !fl && ((d2 <= 0.f) || (d2*d2 <= cb2*var));
                if (__ballot_sync(~0u, fl)) fired = 1;
                unsigned am = __ballot_sync(~0u, amb);
                while (am && !fired) {
                    int l0 = __ffs(am) - 1; am &= am - 1;
                    int has2 = (am != 0u);
                    int l1 = has2 ? (__ffs(am) - 1) : l0;
                    if (has2) am &= am - 1;
                    int pa = __shfl_sync(~0u, p, l0);
                    int pb = __shfl_sync(~0u, p, l1);
                    int ta = pa >> 4, fa = pa & 15;
                    int tb = pb >> 4, fb = pb & 15;
                    const float* xa = tile + (ta + rbase) * TP + fa + cofs;
                    const float* xb = tile + (tb + rbase) * TP + fb + cofs;
                    float a0 = 0.f, a1 = 0.f;
                    #pragma unroll
                    for (int i = 0; i < 16; ++i) {
                        float wv = wbuf[lane + 32*i];
                        a0 = fmaf(wv, xa[66*i], a0);
                        a1 = fmaf(wv, xb[66*i], a1);
                    }
                    #pragma unroll
                    for (int d = 16; d; d >>= 1) {
                        a0 += __shfl_xor_sync(~0u, a0, d);
                        a1 += __shfl_xor_sync(~0u, a1, d);
                    }
                    if (a0 >= THR || (has2 && a1 >= THR)) fired = 1;
                }
            }
            if (fired && lane == 0) {
                atomicOr(&s_pool[cc >> 5], 1u << (cc & 31));
                s_cfired = 1;
            }
            __syncthreads();
        }
    }
    __syncthreads();

    if (tid < 4)
        g_poolw[(s * NFW + fwin) * 4 + tid] = s_pool[tid];

    // ---- fused winner reduction (last CTA) ----
    __threadfence();
    __syncthreads();
    if (tid == 0) s_last = (atomicAdd(&g_done, 1u) == gridDim.x - 1u);
    __syncthreads();
    if (!s_last) return;
    __threadfence();

    if (tid == 0) { s_any = 0; s_key0 = -1; s_key1 = -1; }
    __syncthreads();

    int lk0 = -1, lk1 = -1, localany = 0;
    for (int cell = tid; cell < NC * NFW; cell += 512) {
        int cc = cell / NFW, f = cell % NFW;
        int wword = cc >> 5, wbit = cc & 31;
        unsigned mask = 0; int cnt = 0;
        #pragma unroll
        for (int ss = 0; ss < NS; ++ss) {
            int b = (int)((g_poolw[(ss * NFW + f) * 4 + wword] >> wbit) & 1u);
            mask |= (unsigned)b << ss; cnt += b;
        }
        int e = 8 - cnt; e = e < 0 ? 0 : (e > 7 ? 7 : e);
        int val = (int)((mask >> e) & 1u);
        if (cnt > 0 && val > 0) localany = 1;
        int k0 = ((cnt * val)       << 11) | (2047 - cell);
        int k1 = ((cnt * (val + 8)) << 11) | (2047 - cell);
        if (k0 > lk0) lk0 = k0;
        if (k1 > lk1) lk1 = k1;
    }
    #pragma unroll
    for (int d = 16; d; d >>= 1) {
        lk0 = max(lk0, __shfl_xor_sync(~0u, lk0, d));
        lk1 = max(lk1, __shfl_xor_sync(~0u, lk1, d));
        localany |= __shfl_xor_sync(~0u, localany, d);
    }
    if (lane == 0) {
        atomicMax(&s_key0, lk0);
        atomicMax(&s_key1, lk1);
        if (localany) atomicOr(&s_any, 1);
    }
    __syncthreads();

    if (tid == 0) {
        int key = s_any ? s_key1 : s_key0;
        int total = key >> 11, cell = 2047 - (key & 2047);
        out[0] = total ? (cell / NFW) : -1;
        g_done = 0;
    }
}

extern "C" void kernel_launch(void* const* d_in, const int* in_sizes, int n_in,
                              void* d_out, int out_size)
{
    (void)n_in; (void)out_size;
    const float* X = (const float*)d_in[0];
    const float* W = (const float*)d_in[1];
    if (in_sizes[0] == NS * NC * KT * KF) { const float* t = X; X = W; W = t; }

    const size_t smem = (size_t)SMEM_F * sizeof(float);
    cudaFuncSetAttribute(spyke_kernel,
                         cudaFuncAttributeMaxDynamicSharedMemorySize, (int)smem);
    spyke_kernel<<<NS * NFW, 512, smem>>>(X, W, (int*)d_out);
}

// round 13
// speedup vs baseline: 1.1233x; 1.1233x over previous
#include <cuda_runtime.h>

#define NS 8
#define NC 128
#define KT 32
#define KF 16
#define FREQ 256
#define NFW 15
#define THR 15.0f
#define LPRE 431
#define NPOT 6400
#define MARGIN 0.05f
#define NCAND 16

#define TP 33
#define RP 17
#define RROW_OFF  14224
#define S_OFF     21552
#define X2_OFF    27952
#define RROW2_OFF 34352
#define XP_OFF    41680          /* xpatch[16][512] */
#define SMEM_F    49872          /* 199,488 bytes */

__device__ unsigned g_poolw[NS * NFW * 4];
__device__ unsigned g_done;

__global__ __launch_bounds__(512, 1)
void spyke_kernel(const float* __restrict__ X, const float* __restrict__ W,
                  int* __restrict__ out)
{
    extern __shared__ float sm[];
    float* tile   = sm;
    float* Rrow   = sm + RROW_OFF;
    float* Sarr   = sm + S_OFF;
    float* Varr   = sm + X2_OFF;
    float* Rrow2  = sm + RROW2_OFF;
    float* xpatch = sm + XP_OFF;

    __shared__ unsigned long long s_cand[NCAND];
    __shared__ int s_p[NCAND];
    __shared__ unsigned s_pool[4];
    __shared__ int s_sig_i, s_rcnt, s_qhead, s_last, s_any, s_key0, s_key1;
    __shared__ int s_rem[NC];

    const int s = blockIdx.x / NFW, fwin = blockIdx.x % NFW;
    const int tid = threadIdx.x, sec = s * 400;
    const int lane = tid & 31, wid = tid >> 5;

    if (tid < NCAND) s_cand[tid] = 0ULL;
    if (tid < 4) s_pool[tid] = 0u;
    if (tid == 0) { s_rcnt = 0; s_sig_i = 0; s_qhead = 0; }

    const float* Wsec = W + (size_t)s * NC * 512;

    // ---- stage X window: float4 loads ----
    {
        const float4* X4 = (const float4*)X;
        for (int i = tid; i < LPRE * 8; i += 512) {
            int r = i >> 3, c = i & 7;
            float4 v = X4[(sec + r) * 64 + fwin * 4 + c];
            float* dst = tile + r * TP + c * 4;
            dst[0] = v.x; dst[1] = v.y; dst[2] = v.z; dst[3] = v.w;
        }
    }
    __syncthreads();

    // ---- row sliding sums over kf-window of 16 ----
    if (tid < LPRE) {
        float a = 0.f;
        #pragma unroll
        for (int c = 0; c < 16; ++c) a += tile[tid*TP + c];
        Rrow[tid*RP] = a;
        #pragma unroll 5
        for (int f = 1; f < 16; ++f) {
            a += tile[tid*TP + f + 15] - tile[tid*TP + f - 1];
            Rrow[tid*RP + f] = a;
        }
    }
    __syncthreads();

    // ---- column sliding over kt-window of 32: S + per-region argmax ----
    if (tid < 400) {
        int f = tid & 15, t0 = (tid >> 4) * 16;
        float a = 0.f;
        #pragma unroll 8
        for (int k = 0; k < 32; ++k) a += Rrow[(t0+k)*RP+f];
        unsigned long long lkey[2] = {0ULL, 0ULL};
        int reg0 = t0 / 25;
        for (int t = t0; t < t0 + 16; ++t) {
            int p = t*16 + f;
            Sarr[p] = a;
            unsigned long long key =
                ((unsigned long long)__float_as_uint(a) << 13) | (unsigned)p;
            int ri = (t / 25) - reg0;
            if (key > lkey[ri]) lkey[ri] = key;
            if (t <= 398) a += Rrow[(t+32)*RP+f] - Rrow[t*RP+f];
        }
        atomicMax(&s_cand[reg0], lkey[0]);
        if (lkey[1] && reg0 + 1 < NCAND) atomicMax(&s_cand[reg0 + 1], lkey[1]);
    }
    __syncthreads();

    // ---- sort candidates descending by S ----
    if (tid < NCAND) {
        unsigned long long mykey = s_cand[tid];
        int rank = 0;
        for (int j = 0; j < NCAND; ++j) rank += (s_cand[j] > mykey);
        s_p[rank] = (int)(mykey & 8191ULL);
    }
    __syncthreads();

    // ---- stage all 16 candidate patches ----
    {
        const int gr = tid >> 4, gc = tid & 15;
        #pragma unroll
        for (int k = 0; k < NCAND; ++k) {
            int p = s_p[k], t = p >> 4, f = p & 15;
            xpatch[k * 512 + tid] = tile[(t + gr) * TP + f + gc];
        }
    }
    __syncthreads();

    // ---- per-warp probes: W loaded once per channel, no CTA barriers ----
    const float4* Ws4 = (const float4*)Wsec;
    #pragma unroll 2
    for (int j = 0; j < 8; ++j) {
        int c = wid * 8 + j;
        const float4* Wc = Ws4 + (size_t)c * 128;
        float4 w0 = Wc[lane], w1 = Wc[lane+32], w2 = Wc[lane+64], w3 = Wc[lane+96];
        // candidate 0
        const float4* xp = (const float4*)xpatch;
        float4 x0 = xp[lane], x1 = xp[lane+32], x2 = xp[lane+64], x3 = xp[lane+96];
        float a = 0.f;
        a = fmaf(w0.x, x0.x, a); a = fmaf(w0.y, x0.y, a); a = fmaf(w0.z, x0.z, a); a = fmaf(w0.w, x0.w, a);
        a = fmaf(w1.x, x1.x, a); a = fmaf(w1.y, x1.y, a); a = fmaf(w1.z, x1.z, a); a = fmaf(w1.w, x1.w, a);
        a = fmaf(w2.x, x2.x, a); a = fmaf(w2.y, x2.y, a); a = fmaf(w2.z, x2.z, a); a = fmaf(w2.w, x2.w, a);
        a = fmaf(w3.x, x3.x, a); a = fmaf(w3.y, x3.y, a); a = fmaf(w3.z, x3.z, a); a = fmaf(w3.w, x3.w, a);
        #pragma unroll
        for (int d = 16; d; d >>= 1) a += __shfl_xor_sync(~0u, a, d);
        bool fired = (a >= THR);
        // candidates 1..15, two at a time, same W registers
        for (int k = 1; k < NCAND && !fired; k += 2) {
            int k2 = (k + 1 < NCAND) ? k + 1 : k;
            const float4* xa = (const float4*)(xpatch + k  * 512);
            const float4* xb = (const float4*)(xpatch + k2 * 512);
            float a0 = 0.f, a1 = 0.f;
            float4 ya, yb;
            ya = xa[lane];    yb = xb[lane];
            a0 = fmaf(w0.x, ya.x, a0); a0 = fmaf(w0.y, ya.y, a0); a0 = fmaf(w0.z, ya.z, a0); a0 = fmaf(w0.w, ya.w, a0);
            a1 = fmaf(w0.x, yb.x, a1); a1 = fmaf(w0.y, yb.y, a1); a1 = fmaf(w0.z, yb.z, a1); a1 = fmaf(w0.w, yb.w, a1);
            ya = xa[lane+32]; yb = xb[lane+32];
            a0 = fmaf(w1.x, ya.x, a0); a0 = fmaf(w1.y, ya.y, a0); a0 = fmaf(w1.z, ya.z, a0); a0 = fmaf(w1.w, ya.w, a0);
            a1 = fmaf(w1.x, yb.x, a1); a1 = fmaf(w1.y, yb.y, a1); a1 = fmaf(w1.z, yb.z, a1); a1 = fmaf(w1.w, yb.w, a1);
            ya = xa[lane+64]; yb = xb[lane+64];
            a0 = fmaf(w2.x, ya.x, a0); a0 = fmaf(w2.y, ya.y, a0); a0 = fmaf(w2.z, ya.z, a0); a0 = fmaf(w2.w, ya.w, a0);
            a1 = fmaf(w2.x, yb.x, a1); a1 = fmaf(w2.y, yb.y, a1); a1 = fmaf(w2.z, yb.z, a1); a1 = fmaf(w2.w, yb.w, a1);
            ya = xa[lane+96]; yb = xb[lane+96];
            a0 = fmaf(w3.x, ya.x, a0); a0 = fmaf(w3.y, ya.y, a0); a0 = fmaf(w3.z, ya.z, a0); a0 = fmaf(w3.w, ya.w, a0);
            a1 = fmaf(w3.x, yb.x, a1); a1 = fmaf(w3.y, yb.y, a1); a1 = fmaf(w3.z, yb.z, a1); a1 = fmaf(w3.w, yb.w, a1);
            #pragma unroll
            for (int d = 16; d; d >>= 1) {
                a0 += __shfl_xor_sync(~0u, a0, d);
                a1 += __shfl_xor_sync(~0u, a1, d);
            }
            fired = (fmaxf(a0, a1) >= THR);
        }
        if (fired && lane == 0) atomicOr(&s_pool[c >> 5], 1u << (c & 31));
    }
    __syncthreads();

    // ================= rigorous cold path (rare) =================
    if ((s_pool[0] & s_pool[1] & s_pool[2] & s_pool[3]) != 0xffffffffu) {
        if (tid < LPRE) {
            float a2 = 0.f;
            #pragma unroll
            for (int c = 0; c < 16; ++c) { float x = tile[tid*TP + c]; a2 += x*x; }
            Rrow2[tid*RP] = a2;
            for (int f = 1; f < 16; ++f) {
                float xo = tile[tid*TP + f - 1], xn = tile[tid*TP + f + 15];
                a2 += xn*xn - xo*xo;
                Rrow2[tid*RP + f] = a2;
            }
        }
        __syncthreads();
        if (tid < 400) {
            int f = tid & 15, t0 = (tid >> 4) * 16;
            float a2 = 0.f;
            for (int k = 0; k < 32; ++k) a2 += Rrow2[(t0+k)*RP+f];
            float lsig = 0.f;
            for (int t = t0; t < t0 + 16; ++t) {
                int p = t*16 + f;
                float S = Sarr[p];
                float var = fmaxf(a2 - S*S*(1.0f/512.0f), 0.f);
                Varr[p] = var;
                lsig = fmaxf(lsig, var);
                if (t <= 398) a2 += Rrow2[(t+32)*RP+f] - Rrow2[t*RP+f];
            }
            atomicMax(&s_sig_i, __float_as_int(lsig));
        }
        if (tid < NC && !((s_pool[tid >> 5] >> (tid & 31)) & 1u))
            s_rem[atomicAdd(&s_rcnt, 1)] = tid;
        __syncthreads();

        const float Smax   = Sarr[s_p[0]];
        const float sigMax = sqrtf(__int_as_float(s_sig_i));
        const int   rb     = lane >> 4;
        const int   cofs   = lane & 15;

        // warp-claim queue: zero CTA barriers per channel
        for (;;) {
            int ri;
            if (lane == 0) ri = atomicAdd(&s_qhead, 1);
            ri = __shfl_sync(~0u, ri, 0);
            if (ri >= s_rcnt) break;
            const int cc = s_rem[ri];
            const float* Wr = Wsec + (size_t)cc * 512;
            float wv[16];
            #pragma unroll
            for (int i = 0; i < 16; ++i) wv[i] = Wr[lane + 32*i];
            float ws = 0.f, wq = 0.f;
            #pragma unroll
            for (int i = 0; i < 16; ++i) { ws += wv[i]; wq += wv[i]*wv[i]; }
            #pragma unroll
            for (int d = 16; d; d >>= 1) {
                ws += __shfl_xor_sync(~0u, ws, d);
                wq += __shfl_xor_sync(~0u, wq, d);
            }
            const float cw  = ws;
            const float cb2 = fmaxf(wq - ws*ws*(1.0f/512.0f), 0.f);
            if (cw * Smax * (1.0f/512.0f) + sqrtf(cb2) * sigMax < THR - MARGIN)
                continue;                        // provably never fires
            int fired = 0;
            for (int p0 = 0; p0 < NPOT && !fired; p0 += 32) {
                int p = p0 + lane;
                float S   = Sarr[p];
                float var = Varr[p];
                float base = cw * S * (1.0f/512.0f);
                float d1 = base - (THR + MARGIN);
                float d2 = (THR - MARGIN) - base;
                bool fl  = (d1 >= 0.f) && (d1*d1 >= cb2*var);
                bool amb = !fl && ((d2 <= 0.f) || (d2*d2 <= cb2*var));
                if (__ballot_sync(~0u, fl)) fired = 1;
                unsigned am = __ballot_sync(~0u, amb);
                while (am && !fired) {
                    int l0 = __ffs(am) - 1; am &= am - 1;
                    int pp = __shfl_sync(~0u, p, l0);
                    int t = pp >> 4, f = pp & 15;
                    const float* xr = tile + (t + rb) * TP + f + cofs;
                    float a = 0.f;
                    #pragma unroll
                    for (int i = 0; i < 16; ++i) a = fmaf(wv[i], xr[66*i], a);
                    #pragma unroll
                    for (int d = 16; d; d >>= 1) a += __shfl_xor_sync(~0u, a, d);
                    if (a >= THR) fired = 1;
                }
            }
            if (fired && lane == 0) atomicOr(&s_pool[cc >> 5], 1u << (cc & 31));
        }
        __syncthreads();
    }

    if (tid < 4)
        g_poolw[(s * NFW + fwin) * 4 + tid] = s_pool[tid];

    // ---- fused winner reduction (last CTA) ----
    __threadfence();
    __syncthreads();
    if (tid == 0) s_last = (atomicAdd(&g_done, 1u) == gridDim.x - 1u);
    __syncthreads();
    if (!s_last) return;
    __threadfence();

    if (tid == 0) { s_any = 0; s_key0 = -1; s_key1 = -1; }
    __syncthreads();

    int lk0 = -1, lk1 = -1, localany = 0;
    for (int cell = tid; cell < NC * NFW; cell += 512) {
        int cc = cell / NFW, f = cell % NFW;
        int wword = cc >> 5, wbit = cc & 31;
        unsigned mask = 0; int cnt = 0;
        #pragma unroll
        for (int ss = 0; ss < NS; ++ss) {
            int b = (int)((g_poolw[(ss * NFW + f) * 4 + wword] >> wbit) & 1u);
            mask |= (unsigned)b << ss; cnt += b;
        }
        int e = 8 - cnt; e = e < 0 ? 0 : (e > 7 ? 7 : e);
        int val = (int)((mask >> e) & 1u);
        if (cnt > 0 && val > 0) localany = 1;
        int k0 = ((cnt * val)       << 11) | (2047 - cell);
        int k1 = ((cnt * (val + 8)) << 11) | (2047 - cell);
        if (k0 > lk0) lk0 = k0;
        if (k1 > lk1) lk1 = k1;
    }
    #pragma unroll
    for (int d = 16; d; d >>= 1) {
        lk0 = max(lk0, __shfl_xor_sync(~0u, lk0, d));
        lk1 = max(lk1, __shfl_xor_sync(~0u, lk1, d));
        localany |= __shfl_xor_sync(~0u, localany, d);
    }
    if (lane == 0) {
        atomicMax(&s_key0, lk0);
        atomicMax(&s_key1, lk1);
        if (localany) atomicOr(&s_any, 1);
    }
    __syncthreads();

    if (tid == 0) {
        int key = s_any ? s_key1 : s_key0;
        int total = key >> 11, cell = 2047 - (key & 2047);
        out[0] = total ? (cell / NFW) : -1;
        g_done = 0;
    }
}

extern "C" void kernel_launch(void* const* d_in, const int* in_sizes, int n_in,
                              void* d_out, int out_size)
{
    (void)n_in; (void)out_size;
    const float* X = (const float*)d_in[0];
    const float* W = (const float*)d_in[1];
    if (in_sizes[0] == NS * NC * KT * KF) { const float* t = X; X = W; W = t; }

    const size_t smem = (size_t)SMEM_F * sizeof(float);
    cudaFuncSetAttribute(spyke_kernel,
                         cudaFuncAttributeMaxDynamicSharedMemorySize, (int)smem);
    spyke_kernel<<<NS * NFW, 512, smem>>>(X, W, (int*)d_out);
}